// round 4
// baseline (speedup 1.0000x reference)
#include <cuda_runtime.h>
#include <cuda_fp16.h>
#include <cuda_bf16.h>
#include <math.h>

#define NMAX 50000
#define DIM 128
#define KNBR 16
#define HSW 68   // smem row stride in 32-bit words (64 data + 4 pad; 68%32==4)

// Scratch (static device globals — no allocation allowed)
__device__ __half g_E [(size_t)NMAX * DIM];
__device__ __half g_H1[(size_t)NMAX * DIM];
__device__ __half g_H2[(size_t)NMAX * DIM];
__device__ float  g_C [(size_t)NMAX * 2 * DIM];

// ---------------------------------------------------------------------------
// fp32 -> fp16 elementwise convert (vectorized)
// ---------------------------------------------------------------------------
__global__ void f2h_kernel(const float* __restrict__ in, __half* __restrict__ out, int n4) {
    int i = blockIdx.x * blockDim.x + threadIdx.x;
    if (i < n4) {
        float4 v = __ldg((const float4*)in + i);
        __half2 lo = __floats2half2_rn(v.x, v.y);
        __half2 hi = __floats2half2_rn(v.z, v.w);
        uint2 u;
        u.x = *(unsigned*)&lo;
        u.y = *(unsigned*)&hi;
        ((uint2*)out)[i] = u;
    }
}

// ---------------------------------------------------------------------------
// Mean neighbor aggregation in fp16: out[n] = mean_k in[nbr[n][k]]
// One warp per node; lane owns 4 halves (8B). Accumulate in fp32.
// ---------------------------------------------------------------------------
__global__ void agg_kernel(const __half* __restrict__ in,
                           const int* __restrict__ nbr,
                           __half* __restrict__ out, int N) {
    int warp = (blockIdx.x * blockDim.x + threadIdx.x) >> 5;
    int lane = threadIdx.x & 31;
    if (warp >= N) return;
    const int* nb = nbr + (size_t)warp * KNBR;
    const uint2* in8 = (const uint2*)in;   // 32 uint2 per 128-half row
    float2 a0 = make_float2(0.f, 0.f), a1 = make_float2(0.f, 0.f);
#pragma unroll
    for (int k = 0; k < KNBR; k++) {
        int idx = __ldg(nb + k);
        uint2 u = __ldg(in8 + (size_t)idx * 32 + lane);
        float2 f0 = __half22float2(*(__half2*)&u.x);
        float2 f1 = __half22float2(*(__half2*)&u.y);
        a0.x += f0.x; a0.y += f0.y;
        a1.x += f1.x; a1.y += f1.y;
    }
    const float s = 1.0f / (float)KNBR;
    __half2 h0 = __floats2half2_rn(a0.x * s, a0.y * s);
    __half2 h1 = __floats2half2_rn(a1.x * s, a1.y * s);
    uint2 r;
    r.x = *(unsigned*)&h0;
    r.y = *(unsigned*)&h1;
    ((uint2*)out)[(size_t)warp * 32 + lane] = r;
}

// ---------------------------------------------------------------------------
// fp16 MMA helper
// ---------------------------------------------------------------------------
__device__ __forceinline__ void mma_f16(float* d, const unsigned* a, const unsigned* b) {
    asm("mma.sync.aligned.m16n8k16.row.col.f32.f16.f16.f32 "
        "{%0,%1,%2,%3}, {%4,%5,%6,%7}, {%8,%9}, {%0,%1,%2,%3};"
        : "+f"(d[0]), "+f"(d[1]), "+f"(d[2]), "+f"(d[3])
        : "r"(a[0]), "r"(a[1]), "r"(a[2]), "r"(a[3]), "r"(b[0]), "r"(b[1]));
}

// ---------------------------------------------------------------------------
// C[N,256] = H[N,128] @ Wcat[128,256]   (fp16 inputs, fp32 accumulate)
// Wcat[k][c] = (c<128) ? W1[k][c] : W1[k+128][c-128]
// Ws stored TRANSPOSED in smem: Ws[n][k] halves, row stride HSW words.
// Hs: [64][128] halves, row stride HSW words. Both conflict-free for frags.
// 296 persistent CTAs x 256 threads, 2 CTAs/SM. Warp w owns cols [32w,32w+32).
// ---------------------------------------------------------------------------
extern __shared__ unsigned s_dyn_u[];

__global__ __launch_bounds__(256, 2) void gemm_kernel(const __half* __restrict__ H,
                                                      const float* __restrict__ W1,
                                                      float* __restrict__ C, int N) {
    unsigned* Ws = s_dyn_u;             // [256][HSW] words (halves [256][2*HSW])
    unsigned* Hs = s_dyn_u + 256 * HSW; // [64][HSW] words
    int t = threadIdx.x;
    int lane = t & 31;
    int warp = t >> 5;
    int g  = lane >> 2;    // fragment group (row/col group)
    int tg = lane & 3;     // thread-in-group
    int n0 = warp * 32;

    // Fill Ws (coalesced over W1 columns; one-time per CTA)
    __half* Wsh = (__half*)Ws;
    for (int idx = t; idx < 256 * 128; idx += 256) {
        int k = idx >> 8;
        int n = idx & 255;
        float v = (n < 128) ? W1[k * 128 + n] : W1[(k + 128) * 128 + (n - 128)];
        Wsh[n * (2 * HSW) + k] = __float2half_rn(v);
    }

    int numTiles = (N + 63) >> 6;

    for (int tile = blockIdx.x; tile < numTiles; tile += gridDim.x) {
        int row0 = tile * 64;
        __syncthreads();  // protect Hs reuse (first iter also orders Ws fill)

        // Load H tile (64 rows x 16 uint4) into Hs
        for (int i = t; i < 64 * 16; i += 256) {
            int row = i >> 4;
            int q = i & 15;
            uint4 v = make_uint4(0u, 0u, 0u, 0u);
            if (row0 + row < N)
                v = __ldg((const uint4*)H + (size_t)(row0 + row) * 16 + q);
            *(uint4*)(Hs + row * HSW + q * 4) = v;
        }
        __syncthreads();

        float acc[4][4][4];
#pragma unroll
        for (int mf = 0; mf < 4; mf++)
#pragma unroll
            for (int nf = 0; nf < 4; nf++)
#pragma unroll
                for (int e = 0; e < 4; e++) acc[mf][nf][e] = 0.f;

#pragma unroll
        for (int kk = 0; kk < 8; kk++) {   // 8 chunks of K=16
            unsigned a[4][4];
#pragma unroll
            for (int mf = 0; mf < 4; mf++) {
                int base = (mf * 16 + g) * HSW + kk * 8 + tg;
                a[mf][0] = Hs[base];                 // (g,     2tg..)
                a[mf][1] = Hs[base + 8 * HSW];       // (g+8,   2tg..)
                a[mf][2] = Hs[base + 4];             // (g,     2tg+8..)
                a[mf][3] = Hs[base + 8 * HSW + 4];   // (g+8,   2tg+8..)
            }
            unsigned b[4][2];
#pragma unroll
            for (int nf = 0; nf < 4; nf++) {
                int base = (n0 + nf * 8 + g) * HSW + kk * 8 + tg;
                b[nf][0] = Ws[base];       // k = 2tg..,   col n
                b[nf][1] = Ws[base + 4];   // k = 2tg+8..
            }
#pragma unroll
            for (int mf = 0; mf < 4; mf++)
#pragma unroll
                for (int nf = 0; nf < 4; nf++)
                    mma_f16(acc[mf][nf], a[mf], b[nf]);
        }

        // Epilogue: c0,c1 at (g, 2tg), c2,c3 at (g+8, 2tg)
#pragma unroll
        for (int mf = 0; mf < 4; mf++) {
            int r_lo = row0 + mf * 16 + g;
            int r_hi = r_lo + 8;
#pragma unroll
            for (int nf = 0; nf < 4; nf++) {
                int col = n0 + nf * 8 + tg * 2;
                if (r_lo < N)
                    *(float2*)(C + (size_t)r_lo * 256 + col) =
                        make_float2(acc[mf][nf][0], acc[mf][nf][1]);
                if (r_hi < N)
                    *(float2*)(C + (size_t)r_hi * 256 + col) =
                        make_float2(acc[mf][nf][2], acc[mf][nf][3]);
            }
        }
    }
}

// ---------------------------------------------------------------------------
// Per-pair: h = relu(C[src][0:128] + C[dst][128:256] + b1); logits = h@W2+b2;
// loss_i = logsumexp(softmax(logits)) - softmax(logits)[label]; atomic mean.
// One warp per pair (grid-strided), lane owns 4 features.
// ---------------------------------------------------------------------------
__global__ void pair_kernel(const int* __restrict__ pairs,
                            const int* __restrict__ labels,
                            const float* __restrict__ C,
                            const float* __restrict__ b1,
                            const float* __restrict__ W2,
                            const float* __restrict__ b2,
                            float* __restrict__ out, int B) {
    int lane = threadIdx.x & 31;
    int wib = threadIdx.x >> 5;
    int warpsPerBlock = blockDim.x >> 5;
    int gwarp = blockIdx.x * warpsPerBlock + wib;
    int nwarps = gridDim.x * warpsPerBlock;

    float4 bias = __ldg((const float4*)b1 + lane);
    float w20[4], w21[4];
#pragma unroll
    for (int q = 0; q < 4; q++) {
        w20[q] = __ldg(W2 + (lane * 4 + q) * 2 + 0);
        w21[q] = __ldg(W2 + (lane * 4 + q) * 2 + 1);
    }
    float b2_0 = __ldg(b2 + 0), b2_1 = __ldg(b2 + 1);

    const float4* C4 = (const float4*)C;
    float lsum = 0.f;

    for (int p = gwarp; p < B; p += nwarps) {
        int src = __ldg(pairs + 2 * p);
        int dst = __ldg(pairs + 2 * p + 1);
        float4 a  = __ldg(C4 + (size_t)src * 64 + lane);
        float4 bb = __ldg(C4 + (size_t)dst * 64 + 32 + lane);
        float h0 = fmaxf(a.x + bb.x + bias.x, 0.f);
        float h1 = fmaxf(a.y + bb.y + bias.y, 0.f);
        float h2 = fmaxf(a.z + bb.z + bias.z, 0.f);
        float h3 = fmaxf(a.w + bb.w + bias.w, 0.f);
        float l0 = h0 * w20[0] + h1 * w20[1] + h2 * w20[2] + h3 * w20[3];
        float l1 = h0 * w21[0] + h1 * w21[1] + h2 * w21[2] + h3 * w21[3];
#pragma unroll
        for (int off = 16; off > 0; off >>= 1) {
            l0 += __shfl_down_sync(0xFFFFFFFFu, l0, off);
            l1 += __shfl_down_sync(0xFFFFFFFFu, l1, off);
        }
        if (lane == 0) {
            l0 += b2_0; l1 += b2_1;
            // probs = softmax(logits)
            float m = fmaxf(l0, l1);
            float e0 = expf(l0 - m), e1 = expf(l1 - m);
            float inv = 1.f / (e0 + e1);
            float p0 = e0 * inv, p1 = e1 * inv;
            // logp = probs - logsumexp(probs)
            float mm = fmaxf(p0, p1);
            float lse = mm + logf(expf(p0 - mm) + expf(p1 - mm));
            int lab = __ldg(labels + p);
            float pl = lab ? p1 : p0;
            lsum += (lse - pl);
        }
    }

    __shared__ float ssum[32];
    if (lane == 0) ssum[wib] = lsum;
    __syncthreads();
    if (threadIdx.x == 0) {
        float s = 0.f;
        for (int w = 0; w < warpsPerBlock; w++) s += ssum[w];
        atomicAdd(out, s / (float)B);
    }
}

__global__ void zero_kernel(float* out, int n) {
    int i = blockIdx.x * blockDim.x + threadIdx.x;
    if (i < n) out[i] = 0.f;
}

// ---------------------------------------------------------------------------
extern "C" void kernel_launch(void* const* d_in, const int* in_sizes, int n_in,
                              void* d_out, int out_size) {
    const int*   pairs     = (const int*)d_in[0];
    const int*   labels    = (const int*)d_in[1];
    const int*   neighbors = (const int*)d_in[2];
    const float* embedding = (const float*)d_in[3];
    const float* W1        = (const float*)d_in[4];
    const float* b1        = (const float*)d_in[5];
    const float* W2        = (const float*)d_in[6];
    const float* b2        = (const float*)d_in[7];

    int B = in_sizes[0] / 2;
    int N = in_sizes[2] / KNBR;

    __half *E, *H1, *H2;
    float* C;
    cudaGetSymbolAddress((void**)&E,  g_E);
    cudaGetSymbolAddress((void**)&H1, g_H1);
    cudaGetSymbolAddress((void**)&H2, g_H2);
    cudaGetSymbolAddress((void**)&C,  g_C);

    float* out = (float*)d_out;
    zero_kernel<<<(out_size + 255) / 256, 256>>>(out, out_size);

    // Convert embedding to fp16
    int n4 = N * DIM / 4;
    f2h_kernel<<<(n4 + 255) / 256, 256>>>(embedding, E, n4);

    // 2 aggregation layers (fp16 gathers, fp32 accumulate)
    int aggBlocks = (N + 7) / 8;  // 8 warps/block, warp per node
    agg_kernel<<<aggBlocks, 256>>>(E,  neighbors, H1, N);
    agg_kernel<<<aggBlocks, 256>>>(H1, neighbors, H2, N);

    // Projection GEMM: C = H2 @ Wcat  (fp16 mma, 2 CTAs/SM)
    size_t smem = (size_t)(256 * HSW + 64 * HSW) * sizeof(unsigned);  // 87040 B
    cudaFuncSetAttribute(gemm_kernel, cudaFuncAttributeMaxDynamicSharedMemorySize, (int)smem);
    gemm_kernel<<<296, 256, smem>>>(H2, W1, C, N);

    // Pair loss
    pair_kernel<<<1184, 256>>>(pairs, labels, C, b1, W2, b2, out, B);
}

// round 5
// speedup vs baseline: 1.0731x; 1.0731x over previous
#include <cuda_runtime.h>
#include <cuda_fp16.h>
#include <cuda_bf16.h>
#include <math.h>

#define NMAX 50000
#define DIM 128
#define KNBR 16
#define HSW 68   // smem row stride in 32-bit words (64 data + 4 pad; 68%32==4)

// Scratch (static device globals — no allocation allowed)
__device__ __half g_E [(size_t)NMAX * DIM];
__device__ __half g_H1[(size_t)NMAX * DIM];
__device__ __half g_H2[(size_t)NMAX * DIM];
__device__ __half g_C [(size_t)NMAX * 2 * DIM];

// ---------------------------------------------------------------------------
// fp32 -> fp16 elementwise convert (vectorized); also zeroes the output scalar
// ---------------------------------------------------------------------------
__global__ void f2h_kernel(const float* __restrict__ in, __half* __restrict__ out,
                           int n4, float* __restrict__ loss_out, int loss_n) {
    int i = blockIdx.x * blockDim.x + threadIdx.x;
    if (blockIdx.x == 0 && threadIdx.x < (unsigned)loss_n) loss_out[threadIdx.x] = 0.f;
    if (i < n4) {
        float4 v = __ldg((const float4*)in + i);
        __half2 lo = __floats2half2_rn(v.x, v.y);
        __half2 hi = __floats2half2_rn(v.z, v.w);
        uint2 u;
        u.x = *(unsigned*)&lo;
        u.y = *(unsigned*)&hi;
        ((uint2*)out)[i] = u;
    }
}

// ---------------------------------------------------------------------------
// Mean neighbor aggregation, fp16 throughout: out[n] = mean_k in[nbr[n][k]]
// One warp handles TWO nodes: lanes 0-15 node 2w, lanes 16-31 node 2w+1.
// Each lane loads 16B (8 halves) per neighbor; accumulate with HADD2.
// ---------------------------------------------------------------------------
__global__ void agg_kernel(const __half* __restrict__ in,
                           const int* __restrict__ nbr,
                           __half* __restrict__ out, int N) {
    int gw = (blockIdx.x * blockDim.x + threadIdx.x) >> 5;
    int lane = threadIdx.x & 31;
    int node = gw * 2 + (lane >> 4);
    if (node >= N) return;
    int sl = lane & 15;                       // 16 lanes cover one 256B row
    const int* nb = nbr + (size_t)node * KNBR;
    const uint4* in16 = (const uint4*)in;     // 16 uint4 per 128-half row
    __half2 z = __float2half2_rn(0.f);
    __half2 a0 = z, a1 = z, a2 = z, a3 = z;
#pragma unroll
    for (int k = 0; k < KNBR; k++) {
        int idx = __ldg(nb + k);
        uint4 v = __ldg(in16 + (size_t)idx * 16 + sl);
        a0 = __hadd2(a0, *(__half2*)&v.x);
        a1 = __hadd2(a1, *(__half2*)&v.y);
        a2 = __hadd2(a2, *(__half2*)&v.z);
        a3 = __hadd2(a3, *(__half2*)&v.w);
    }
    __half2 s = __float2half2_rn(1.0f / (float)KNBR);
    a0 = __hmul2(a0, s); a1 = __hmul2(a1, s);
    a2 = __hmul2(a2, s); a3 = __hmul2(a3, s);
    uint4 r;
    r.x = *(unsigned*)&a0; r.y = *(unsigned*)&a1;
    r.z = *(unsigned*)&a2; r.w = *(unsigned*)&a3;
    ((uint4*)out)[(size_t)node * 16 + sl] = r;
}

// ---------------------------------------------------------------------------
// fp16 MMA + ldmatrix helpers
// ---------------------------------------------------------------------------
__device__ __forceinline__ void mma_f16(float* d, const unsigned* a, const unsigned* b) {
    asm("mma.sync.aligned.m16n8k16.row.col.f32.f16.f16.f32 "
        "{%0,%1,%2,%3}, {%4,%5,%6,%7}, {%8,%9}, {%0,%1,%2,%3};"
        : "+f"(d[0]), "+f"(d[1]), "+f"(d[2]), "+f"(d[3])
        : "r"(a[0]), "r"(a[1]), "r"(a[2]), "r"(a[3]), "r"(b[0]), "r"(b[1]));
}

__device__ __forceinline__ void ldsm_x4(unsigned* r, unsigned addr) {
    asm volatile("ldmatrix.sync.aligned.m8n8.x4.shared.b16 {%0,%1,%2,%3}, [%4];"
                 : "=r"(r[0]), "=r"(r[1]), "=r"(r[2]), "=r"(r[3]) : "r"(addr));
}

// ---------------------------------------------------------------------------
// C[N,256] = H[N,128] @ Wcat[128,256]   (fp16 in, fp32 acc, fp16 out)
// Wcat[k][c] = (c<128) ? W1[k][c] : W1[k+128][c-128]
// Ws transposed in smem: [256 n][136 halves k], Hs: [64 m][136 halves k].
// Fragments loaded via ldmatrix.x4 (6 LDSM + 16 MMA per K=16 chunk).
// 296 persistent CTAs x 256 threads, 2 CTAs/SM. Warp w owns cols [32w,32w+32).
// ---------------------------------------------------------------------------
extern __shared__ unsigned s_dyn_u[];

__global__ __launch_bounds__(256, 2) void gemm_kernel(const __half* __restrict__ H,
                                                      const float* __restrict__ W1,
                                                      __half* __restrict__ C, int N) {
    unsigned* Ws = s_dyn_u;             // words; halves [256][136]
    unsigned* Hs = s_dyn_u + 256 * HSW; // words; halves [64][136]
    int t = threadIdx.x;
    int lane = t & 31;
    int warp = t >> 5;
    int g  = lane >> 2;    // fragment group
    int tg = lane & 3;     // thread-in-group
    int n0 = warp * 32;

    // Fill Ws (coalesced over W1 columns; one-time per CTA)
    __half* Wsh = (__half*)Ws;
    for (int idx = t; idx < 256 * 128; idx += 256) {
        int k = idx >> 8;
        int n = idx & 255;
        float v = (n < 128) ? W1[k * 128 + n] : W1[(k + 128) * 128 + (n - 128)];
        Wsh[n * (2 * HSW) + k] = __float2half_rn(v);
    }

    // Per-lane ldmatrix base addresses (byte offsets into smem)
    unsigned hs_base = (unsigned)__cvta_generic_to_shared(Hs);
    unsigned ws_base = (unsigned)__cvta_generic_to_shared(Ws);
    // A: matrices {rows 0-7 klo, rows 8-15 klo, rows 0-7 khi, rows 8-15 khi}
    unsigned a_row = lane & 15;             // row within 16-row frag
    unsigned a_koff = (lane >> 4) * 8;      // 0 or 8 halves
    // B x4 #1: {n0+r klo, n0+r khi, n0+8+r klo, n0+8+r khi}
    unsigned b_n   = (lane & 7) + ((lane >> 4) << 3);   // +8 for lanes>=16
    unsigned b_koff = ((lane >> 3) & 1) << 3;           // 8 for mi 1,3

    int numTiles = (N + 63) >> 6;

    for (int tile = blockIdx.x; tile < numTiles; tile += gridDim.x) {
        int row0 = tile * 64;
        __syncthreads();  // protect Hs reuse (first iter also orders Ws fill)

        // Load H tile (64 rows x 16 uint4) into Hs
        for (int i = t; i < 64 * 16; i += 256) {
            int row = i >> 4;
            int q = i & 15;
            uint4 v = make_uint4(0u, 0u, 0u, 0u);
            if (row0 + row < N)
                v = __ldg((const uint4*)H + (size_t)(row0 + row) * 16 + q);
            *(uint4*)(Hs + row * HSW + q * 4) = v;
        }
        __syncthreads();

        float acc[4][4][4];
#pragma unroll
        for (int mf = 0; mf < 4; mf++)
#pragma unroll
            for (int nf = 0; nf < 4; nf++)
#pragma unroll
                for (int e = 0; e < 4; e++) acc[mf][nf][e] = 0.f;

#pragma unroll
        for (int kk = 0; kk < 8; kk++) {   // 8 chunks of K=16
            unsigned k0 = kk * 16;         // halves
            unsigned a[4][4];
#pragma unroll
            for (int mf = 0; mf < 4; mf++) {
                unsigned addr = hs_base +
                    ((mf * 16 + a_row) * (2 * HSW) + k0 + a_koff) * 2;
                ldsm_x4(a[mf], addr);
            }
            unsigned b[4][2];
            {
                unsigned addr1 = ws_base +
                    ((n0 + b_n) * (2 * HSW) + k0 + b_koff) * 2;
                unsigned r1[4], r2[4];
                ldsm_x4(r1, addr1);                       // nf 0,1
                ldsm_x4(r2, addr1 + 16 * (2 * HSW) * 2);  // nf 2,3
                b[0][0] = r1[0]; b[0][1] = r1[1];
                b[1][0] = r1[2]; b[1][1] = r1[3];
                b[2][0] = r2[0]; b[2][1] = r2[1];
                b[3][0] = r2[2]; b[3][1] = r2[3];
            }
#pragma unroll
            for (int mf = 0; mf < 4; mf++)
#pragma unroll
                for (int nf = 0; nf < 4; nf++)
                    mma_f16(acc[mf][nf], a[mf], b[nf]);
        }

        // Epilogue -> fp16 C. c0,c1 at (g, 2tg), c2,c3 at (g+8, 2tg)
        unsigned* C32 = (unsigned*)C;   // half2 units; row = 128
#pragma unroll
        for (int mf = 0; mf < 4; mf++) {
            int r_lo = row0 + mf * 16 + g;
            int r_hi = r_lo + 8;
#pragma unroll
            for (int nf = 0; nf < 4; nf++) {
                int colh = (n0 + nf * 8 + tg * 2) >> 1;   // half2 index
                if (r_lo < N) {
                    __half2 h = __floats2half2_rn(acc[mf][nf][0], acc[mf][nf][1]);
                    C32[(size_t)r_lo * 128 + colh] = *(unsigned*)&h;
                }
                if (r_hi < N) {
                    __half2 h = __floats2half2_rn(acc[mf][nf][2], acc[mf][nf][3]);
                    C32[(size_t)r_hi * 128 + colh] = *(unsigned*)&h;
                }
            }
        }
    }
}

// ---------------------------------------------------------------------------
// Per-pair: h = relu(C[src][0:128] + C[dst][128:256] + b1); logits = h@W2+b2;
// loss_i = logsumexp(softmax(logits)) - softmax(logits)[label]; atomic mean.
// One warp per pair (grid-strided), lane owns 4 features. C is fp16.
// ---------------------------------------------------------------------------
__global__ void pair_kernel(const int* __restrict__ pairs,
                            const int* __restrict__ labels,
                            const __half* __restrict__ C,
                            const float* __restrict__ b1,
                            const float* __restrict__ W2,
                            const float* __restrict__ b2,
                            float* __restrict__ out, int B) {
    int lane = threadIdx.x & 31;
    int wib = threadIdx.x >> 5;
    int warpsPerBlock = blockDim.x >> 5;
    int gwarp = blockIdx.x * warpsPerBlock + wib;
    int nwarps = gridDim.x * warpsPerBlock;

    float4 bias = __ldg((const float4*)b1 + lane);
    float w20[4], w21[4];
#pragma unroll
    for (int q = 0; q < 4; q++) {
        w20[q] = __ldg(W2 + (lane * 4 + q) * 2 + 0);
        w21[q] = __ldg(W2 + (lane * 4 + q) * 2 + 1);
    }
    float b2_0 = __ldg(b2 + 0), b2_1 = __ldg(b2 + 1);

    const uint2* C8 = (const uint2*)C;   // 4 halves per uint2; row = 64 uint2
    float lsum = 0.f;

    for (int p = gwarp; p < B; p += nwarps) {
        int src = __ldg(pairs + 2 * p);
        int dst = __ldg(pairs + 2 * p + 1);
        uint2 ua = __ldg(C8 + (size_t)src * 64 + lane);        // cols 4l..4l+3
        uint2 ub = __ldg(C8 + (size_t)dst * 64 + 32 + lane);   // cols 128+4l..
        float2 a01 = __half22float2(*(__half2*)&ua.x);
        float2 a23 = __half22float2(*(__half2*)&ua.y);
        float2 c01 = __half22float2(*(__half2*)&ub.x);
        float2 c23 = __half22float2(*(__half2*)&ub.y);
        float h0 = fmaxf(a01.x + c01.x + bias.x, 0.f);
        float h1 = fmaxf(a01.y + c01.y + bias.y, 0.f);
        float h2 = fmaxf(a23.x + c23.x + bias.z, 0.f);
        float h3 = fmaxf(a23.y + c23.y + bias.w, 0.f);
        float l0 = h0 * w20[0] + h1 * w20[1] + h2 * w20[2] + h3 * w20[3];
        float l1 = h0 * w21[0] + h1 * w21[1] + h2 * w21[2] + h3 * w21[3];
#pragma unroll
        for (int off = 16; off > 0; off >>= 1) {
            l0 += __shfl_down_sync(0xFFFFFFFFu, l0, off);
            l1 += __shfl_down_sync(0xFFFFFFFFu, l1, off);
        }
        if (lane == 0) {
            l0 += b2_0; l1 += b2_1;
            // probs = softmax(logits)
            float m = fmaxf(l0, l1);
            float e0 = expf(l0 - m), e1 = expf(l1 - m);
            float inv = 1.f / (e0 + e1);
            float p0 = e0 * inv, p1 = e1 * inv;
            // logp = probs - logsumexp(probs)
            float mm = fmaxf(p0, p1);
            float lse = mm + logf(expf(p0 - mm) + expf(p1 - mm));
            int lab = __ldg(labels + p);
            float pl = lab ? p1 : p0;
            lsum += (lse - pl);
        }
    }

    __shared__ float ssum[32];
    if (lane == 0) ssum[wib] = lsum;
    __syncthreads();
    if (threadIdx.x == 0) {
        float s = 0.f;
        for (int w = 0; w < warpsPerBlock; w++) s += ssum[w];
        atomicAdd(out, s / (float)B);
    }
}

// ---------------------------------------------------------------------------
extern "C" void kernel_launch(void* const* d_in, const int* in_sizes, int n_in,
                              void* d_out, int out_size) {
    const int*   pairs     = (const int*)d_in[0];
    const int*   labels    = (const int*)d_in[1];
    const int*   neighbors = (const int*)d_in[2];
    const float* embedding = (const float*)d_in[3];
    const float* W1        = (const float*)d_in[4];
    const float* b1        = (const float*)d_in[5];
    const float* W2        = (const float*)d_in[6];
    const float* b2        = (const float*)d_in[7];

    int B = in_sizes[0] / 2;
    int N = in_sizes[2] / KNBR;

    __half *E, *H1, *H2, *C;
    cudaGetSymbolAddress((void**)&E,  g_E);
    cudaGetSymbolAddress((void**)&H1, g_H1);
    cudaGetSymbolAddress((void**)&H2, g_H2);
    cudaGetSymbolAddress((void**)&C,  g_C);

    float* out = (float*)d_out;

    // Convert embedding to fp16 (also zeroes the loss accumulator)
    int n4 = N * DIM / 4;
    f2h_kernel<<<(n4 + 255) / 256, 256>>>(embedding, E, n4, out, out_size);

    // 2 aggregation layers (fp16 gathers, half2 accumulate; warp = 2 nodes)
    int aggBlocks = (N / 2 + 7) / 8;   // 8 warps/block, 2 nodes/warp
    agg_kernel<<<aggBlocks, 256>>>(E,  neighbors, H1, N);
    agg_kernel<<<aggBlocks, 256>>>(H1, neighbors, H2, N);

    // Projection GEMM: C = H2 @ Wcat  (fp16 mma + ldmatrix, 2 CTAs/SM)
    size_t smem = (size_t)(256 * HSW + 64 * HSW) * sizeof(unsigned);  // 87040 B
    cudaFuncSetAttribute(gemm_kernel, cudaFuncAttributeMaxDynamicSharedMemorySize, (int)smem);
    gemm_kernel<<<296, 256, smem>>>(H2, W1, C, N);

    // Pair loss (fp16 C gathers)
    pair_kernel<<<1184, 256>>>(pairs, labels, C, b1, W2, b2, out, B);
}

// round 6
// speedup vs baseline: 1.2038x; 1.1218x over previous
#include <cuda_runtime.h>
#include <cuda_fp16.h>
#include <cuda_bf16.h>
#include <math.h>

#define NMAX 50000
#define DIM 128
#define KNBR 16
#define HSW 68   // smem row stride in 32-bit words (64 data + 4 pad; 68%32==4)

// Scratch (static device globals — no allocation allowed)
__device__ __half g_E [(size_t)NMAX * DIM];
__device__ __half g_H1[(size_t)NMAX * DIM];
__device__ __half g_H2[(size_t)NMAX * DIM];
__device__ __half g_C [(size_t)NMAX * 2 * DIM];

// ---------------------------------------------------------------------------
// fp32 -> fp16 elementwise convert (vectorized); also zeroes the output scalar
// ---------------------------------------------------------------------------
__global__ void f2h_kernel(const float* __restrict__ in, __half* __restrict__ out,
                           int n4, float* __restrict__ loss_out, int loss_n) {
    int i = blockIdx.x * blockDim.x + threadIdx.x;
    if (blockIdx.x == 0 && threadIdx.x < (unsigned)loss_n) loss_out[threadIdx.x] = 0.f;
    if (i < n4) {
        float4 v = __ldg((const float4*)in + i);
        __half2 lo = __floats2half2_rn(v.x, v.y);
        __half2 hi = __floats2half2_rn(v.z, v.w);
        uint2 u;
        u.x = *(unsigned*)&lo;
        u.y = *(unsigned*)&hi;
        ((uint2*)out)[i] = u;
    }
}

// ---------------------------------------------------------------------------
// Mean neighbor aggregation, fp16 throughout: out[n] = mean_k in[nbr[n][k]]
// One warp handles TWO nodes: lanes 0-15 node 2w, lanes 16-31 node 2w+1.
// Each lane loads 16B (8 halves) per neighbor; accumulate with HADD2.
// ---------------------------------------------------------------------------
__global__ void agg_kernel(const __half* __restrict__ in,
                           const int* __restrict__ nbr,
                           __half* __restrict__ out, int N) {
    int gw = (blockIdx.x * blockDim.x + threadIdx.x) >> 5;
    int lane = threadIdx.x & 31;
    int node = gw * 2 + (lane >> 4);
    if (node >= N) return;
    int sl = lane & 15;                       // 16 lanes cover one 256B row
    const int* nb = nbr + (size_t)node * KNBR;
    const uint4* in16 = (const uint4*)in;     // 16 uint4 per 128-half row
    __half2 z = __float2half2_rn(0.f);
    __half2 a0 = z, a1 = z, a2 = z, a3 = z;
#pragma unroll
    for (int k = 0; k < KNBR; k++) {
        int idx = __ldg(nb + k);
        uint4 v = __ldg(in16 + (size_t)idx * 16 + sl);
        a0 = __hadd2(a0, *(__half2*)&v.x);
        a1 = __hadd2(a1, *(__half2*)&v.y);
        a2 = __hadd2(a2, *(__half2*)&v.z);
        a3 = __hadd2(a3, *(__half2*)&v.w);
    }
    __half2 s = __float2half2_rn(1.0f / (float)KNBR);
    a0 = __hmul2(a0, s); a1 = __hmul2(a1, s);
    a2 = __hmul2(a2, s); a3 = __hmul2(a3, s);
    uint4 r;
    r.x = *(unsigned*)&a0; r.y = *(unsigned*)&a1;
    r.z = *(unsigned*)&a2; r.w = *(unsigned*)&a3;
    ((uint4*)out)[(size_t)node * 16 + sl] = r;
}

// ---------------------------------------------------------------------------
// fp16 MMA + ldmatrix helpers
// ---------------------------------------------------------------------------
__device__ __forceinline__ void mma_f16(float* d, const unsigned* a, const unsigned* b) {
    asm("mma.sync.aligned.m16n8k16.row.col.f32.f16.f16.f32 "
        "{%0,%1,%2,%3}, {%4,%5,%6,%7}, {%8,%9}, {%0,%1,%2,%3};"
        : "+f"(d[0]), "+f"(d[1]), "+f"(d[2]), "+f"(d[3])
        : "r"(a[0]), "r"(a[1]), "r"(a[2]), "r"(a[3]), "r"(b[0]), "r"(b[1]));
}

__device__ __forceinline__ void ldsm_x4(unsigned* r, unsigned addr) {
    asm volatile("ldmatrix.sync.aligned.m8n8.x4.shared.b16 {%0,%1,%2,%3}, [%4];"
                 : "=r"(r[0]), "=r"(r[1]), "=r"(r[2]), "=r"(r[3]) : "r"(addr));
}

// ---------------------------------------------------------------------------
// C[N,256] = H[N,128] @ Wcat[128,256]   (fp16 in, fp32 acc, fp16 out)
// N-split: CTA handles a fixed 128-col half (bid&1). CTA tile: 64 x 128.
// Ws (transposed [128 n][136 halves k]) = 34.8KB, Hs [64][136] = 17.4KB
//   -> 52.2KB/CTA -> 3 CTAs/SM, 24 warps/SM.
// Warps 2(m) x 4(n); warp tile 32x32; acc = 2x4 frags (32 regs).
// H tiles register-double-buffered: LDG next tile before compute, STS after.
// ---------------------------------------------------------------------------
extern __shared__ unsigned s_dyn_u[];

__global__ __launch_bounds__(256, 3) void gemm_kernel(const __half* __restrict__ H,
                                                      const float* __restrict__ W1,
                                                      __half* __restrict__ C, int N) {
    unsigned* Ws = s_dyn_u;             // words; halves [128][136]
    unsigned* Hs = s_dyn_u + 128 * HSW; // words; halves [64][136]
    int t = threadIdx.x;
    int lane = t & 31;
    int warp = t >> 5;
    int mwarp = warp >> 2;      // 0..1
    int nwarp = warp & 3;       // 0..3
    int g  = lane >> 2;         // fragment group
    int tg = lane & 3;          // thread-in-group
    int n0 = nwarp * 32;        // local col base within the 128-col half
    int half = blockIdx.x & 1;  // which 128-col half of Wcat

    // Fill Ws for this half: Ws[n][k] = Wcat[k][half*128+n] = W1[k+half*128][n]
    __half* Wsh = (__half*)Ws;
    for (int idx = t; idx < 128 * 128; idx += 256) {
        int k = idx >> 7;
        int n = idx & 127;
        float v = W1[(k + half * 128) * 128 + n];
        Wsh[n * (2 * HSW) + k] = __float2half_rn(v);
    }

    // Per-lane ldmatrix address components (verified layout from prev round)
    unsigned hs_base = (unsigned)__cvta_generic_to_shared(Hs);
    unsigned ws_base = (unsigned)__cvta_generic_to_shared(Ws);
    unsigned a_row  = lane & 15;
    unsigned a_koff = (lane >> 4) * 8;
    unsigned b_n    = (lane & 7) + ((lane >> 4) << 3);
    unsigned b_koff = ((lane >> 3) & 1) << 3;

    int numRowTiles = (N + 63) >> 6;
    int stride = gridDim.x >> 1;
    int rt0 = blockIdx.x >> 1;

    // Prefetch first tile into registers (4 x uint4 per thread)
    uint4 pre[4];
    {
        int row0 = rt0 * 64;
#pragma unroll
        for (int j = 0; j < 4; j++) {
            int i = t + j * 256;
            int row = i >> 4, q = i & 15;
            pre[j] = make_uint4(0u, 0u, 0u, 0u);
            if (rt0 < numRowTiles && row0 + row < N)
                pre[j] = __ldg((const uint4*)H + (size_t)(row0 + row) * 16 + q);
        }
    }

    for (int rt = rt0; rt < numRowTiles; rt += stride) {
        int row0 = rt * 64;
        __syncthreads();  // Hs free (first iter: also orders Ws fill)
        // Commit prefetched tile to smem
#pragma unroll
        for (int j = 0; j < 4; j++) {
            int i = t + j * 256;
            int row = i >> 4, q = i & 15;
            *(uint4*)(Hs + row * HSW + q * 4) = pre[j];
        }
        __syncthreads();

        // Issue LDG for the NEXT tile (overlaps with compute below)
        int rtn = rt + stride;
        if (rtn < numRowTiles) {
            int rown0 = rtn * 64;
#pragma unroll
            for (int j = 0; j < 4; j++) {
                int i = t + j * 256;
                int row = i >> 4, q = i & 15;
                pre[j] = make_uint4(0u, 0u, 0u, 0u);
                if (rown0 + row < N)
                    pre[j] = __ldg((const uint4*)H + (size_t)(rown0 + row) * 16 + q);
            }
        }

        float acc[2][4][4];
#pragma unroll
        for (int mf = 0; mf < 2; mf++)
#pragma unroll
            for (int nf = 0; nf < 4; nf++)
#pragma unroll
                for (int e = 0; e < 4; e++) acc[mf][nf][e] = 0.f;

#pragma unroll
        for (int kk = 0; kk < 8; kk++) {   // 8 chunks of K=16
            unsigned k0 = kk * 16;         // halves
            unsigned a[2][4];
#pragma unroll
            for (int mf = 0; mf < 2; mf++) {
                unsigned addr = hs_base +
                    ((mwarp * 32 + mf * 16 + a_row) * (2 * HSW) + k0 + a_koff) * 2;
                ldsm_x4(a[mf], addr);
            }
            unsigned b[4][2];
            {
                unsigned addr1 = ws_base +
                    ((n0 + b_n) * (2 * HSW) + k0 + b_koff) * 2;
                unsigned r1[4], r2[4];
                ldsm_x4(r1, addr1);                       // nf 0,1
                ldsm_x4(r2, addr1 + 16 * (2 * HSW) * 2);  // nf 2,3
                b[0][0] = r1[0]; b[0][1] = r1[1];
                b[1][0] = r1[2]; b[1][1] = r1[3];
                b[2][0] = r2[0]; b[2][1] = r2[1];
                b[3][0] = r2[2]; b[3][1] = r2[3];
            }
#pragma unroll
            for (int mf = 0; mf < 2; mf++)
#pragma unroll
                for (int nf = 0; nf < 4; nf++)
                    mma_f16(acc[mf][nf], a[mf], b[nf]);
        }

        // Epilogue -> fp16 C. c0,c1 at (g, 2tg), c2,c3 at (g+8, 2tg)
        unsigned* C32 = (unsigned*)C;   // half2 units; row = 128 half2
#pragma unroll
        for (int mf = 0; mf < 2; mf++) {
            int r_lo = row0 + mwarp * 32 + mf * 16 + g;
            int r_hi = r_lo + 8;
#pragma unroll
            for (int nf = 0; nf < 4; nf++) {
                int colh = (half * 128 + n0 + nf * 8 + tg * 2) >> 1;
                if (r_lo < N) {
                    __half2 h = __floats2half2_rn(acc[mf][nf][0], acc[mf][nf][1]);
                    C32[(size_t)r_lo * 128 + colh] = *(unsigned*)&h;
                }
                if (r_hi < N) {
                    __half2 h = __floats2half2_rn(acc[mf][nf][2], acc[mf][nf][3]);
                    C32[(size_t)r_hi * 128 + colh] = *(unsigned*)&h;
                }
            }
        }
    }
}

// ---------------------------------------------------------------------------
// Per-pair: h = relu(C[src][0:128] + C[dst][128:256] + b1); logits = h@W2+b2;
// loss_i = logsumexp(softmax(logits)) - softmax(logits)[label]; atomic mean.
// One warp per pair (grid-strided), lane owns 4 features. C is fp16.
// ---------------------------------------------------------------------------
__global__ void pair_kernel(const int* __restrict__ pairs,
                            const int* __restrict__ labels,
                            const __half* __restrict__ C,
                            const float* __restrict__ b1,
                            const float* __restrict__ W2,
                            const float* __restrict__ b2,
                            float* __restrict__ out, int B) {
    int lane = threadIdx.x & 31;
    int wib = threadIdx.x >> 5;
    int warpsPerBlock = blockDim.x >> 5;
    int gwarp = blockIdx.x * warpsPerBlock + wib;
    int nwarps = gridDim.x * warpsPerBlock;

    float4 bias = __ldg((const float4*)b1 + lane);
    float w20[4], w21[4];
#pragma unroll
    for (int q = 0; q < 4; q++) {
        w20[q] = __ldg(W2 + (lane * 4 + q) * 2 + 0);
        w21[q] = __ldg(W2 + (lane * 4 + q) * 2 + 1);
    }
    float b2_0 = __ldg(b2 + 0), b2_1 = __ldg(b2 + 1);

    const uint2* C8 = (const uint2*)C;   // 4 halves per uint2; row = 64 uint2
    float lsum = 0.f;

    for (int p = gwarp; p < B; p += nwarps) {
        int src = __ldg(pairs + 2 * p);
        int dst = __ldg(pairs + 2 * p + 1);
        uint2 ua = __ldg(C8 + (size_t)src * 64 + lane);        // cols 4l..4l+3
        uint2 ub = __ldg(C8 + (size_t)dst * 64 + 32 + lane);   // cols 128+4l..
        float2 a01 = __half22float2(*(__half2*)&ua.x);
        float2 a23 = __half22float2(*(__half2*)&ua.y);
        float2 c01 = __half22float2(*(__half2*)&ub.x);
        float2 c23 = __half22float2(*(__half2*)&ub.y);
        float h0 = fmaxf(a01.x + c01.x + bias.x, 0.f);
        float h1 = fmaxf(a01.y + c01.y + bias.y, 0.f);
        float h2 = fmaxf(a23.x + c23.x + bias.z, 0.f);
        float h3 = fmaxf(a23.y + c23.y + bias.w, 0.f);
        float l0 = h0 * w20[0] + h1 * w20[1] + h2 * w20[2] + h3 * w20[3];
        float l1 = h0 * w21[0] + h1 * w21[1] + h2 * w21[2] + h3 * w21[3];
#pragma unroll
        for (int off = 16; off > 0; off >>= 1) {
            l0 += __shfl_down_sync(0xFFFFFFFFu, l0, off);
            l1 += __shfl_down_sync(0xFFFFFFFFu, l1, off);
        }
        if (lane == 0) {
            l0 += b2_0; l1 += b2_1;
            // probs = softmax(logits)
            float m = fmaxf(l0, l1);
            float e0 = expf(l0 - m), e1 = expf(l1 - m);
            float inv = 1.f / (e0 + e1);
            float p0 = e0 * inv, p1 = e1 * inv;
            // logp = probs - logsumexp(probs)
            float mm = fmaxf(p0, p1);
            float lse = mm + logf(expf(p0 - mm) + expf(p1 - mm));
            int lab = __ldg(labels + p);
            float pl = lab ? p1 : p0;
            lsum += (lse - pl);
        }
    }

    __shared__ float ssum[32];
    if (lane == 0) ssum[wib] = lsum;
    __syncthreads();
    if (threadIdx.x == 0) {
        float s = 0.f;
        for (int w = 0; w < warpsPerBlock; w++) s += ssum[w];
        atomicAdd(out, s / (float)B);
    }
}

// ---------------------------------------------------------------------------
extern "C" void kernel_launch(void* const* d_in, const int* in_sizes, int n_in,
                              void* d_out, int out_size) {
    const int*   pairs     = (const int*)d_in[0];
    const int*   labels    = (const int*)d_in[1];
    const int*   neighbors = (const int*)d_in[2];
    const float* embedding = (const float*)d_in[3];
    const float* W1        = (const float*)d_in[4];
    const float* b1        = (const float*)d_in[5];
    const float* W2        = (const float*)d_in[6];
    const float* b2        = (const float*)d_in[7];

    int B = in_sizes[0] / 2;
    int N = in_sizes[2] / KNBR;

    __half *E, *H1, *H2, *C;
    cudaGetSymbolAddress((void**)&E,  g_E);
    cudaGetSymbolAddress((void**)&H1, g_H1);
    cudaGetSymbolAddress((void**)&H2, g_H2);
    cudaGetSymbolAddress((void**)&C,  g_C);

    float* out = (float*)d_out;

    // Convert embedding to fp16 (also zeroes the loss accumulator)
    int n4 = N * DIM / 4;
    f2h_kernel<<<(n4 + 255) / 256, 256>>>(embedding, E, n4, out, out_size);

    // 2 aggregation layers (fp16 gathers, half2 accumulate; warp = 2 nodes)
    int aggBlocks = (N / 2 + 7) / 8;   // 8 warps/block, 2 nodes/warp
    agg_kernel<<<aggBlocks, 256>>>(E,  neighbors, H1, N);
    agg_kernel<<<aggBlocks, 256>>>(H1, neighbors, H2, N);

    // Projection GEMM: N-split halves, 3 CTAs/SM, register double-buffer
    size_t smem = (size_t)(128 * HSW + 64 * HSW) * sizeof(unsigned);  // 52224 B
    cudaFuncSetAttribute(gemm_kernel, cudaFuncAttributeMaxDynamicSharedMemorySize, (int)smem);
    gemm_kernel<<<444, 256, smem>>>(H2, W1, C, N);

    // Pair loss (fp16 C gathers)
    pair_kernel<<<1184, 256>>>(pairs, labels, C, b1, W2, b2, out, B);
}

// round 8
// speedup vs baseline: 1.2706x; 1.0555x over previous
#include <cuda_runtime.h>
#include <cuda_fp16.h>
#include <cuda_bf16.h>
#include <math.h>

#define NMAX 50000
#define DIM 128
#define KNBR 16
#define HSW 68   // smem row stride in 32-bit words (64 data + 4 pad; 68%32==4)

// Scratch (static device globals — no allocation allowed)
__device__ __half g_E [(size_t)NMAX * DIM];
__device__ __half g_H1[(size_t)NMAX * DIM];
__device__ __half g_H2[(size_t)NMAX * DIM];
__device__ __half g_C [(size_t)NMAX * 2 * DIM];
__device__ __half g_Wh[256 * 128];   // Wcat^T as [n][k] fp16, row-major

// ---------------------------------------------------------------------------
// fp32 -> fp16 elementwise convert (vectorized); also zeroes the output scalar
// ---------------------------------------------------------------------------
__global__ void f2h_kernel(const float* __restrict__ in, __half* __restrict__ out,
                           int n4, float* __restrict__ loss_out, int loss_n) {
    int i = blockIdx.x * blockDim.x + threadIdx.x;
    if (blockIdx.x == 0 && threadIdx.x < (unsigned)loss_n) loss_out[threadIdx.x] = 0.f;
    if (i < n4) {
        float4 v = __ldg((const float4*)in + i);
        __half2 lo = __floats2half2_rn(v.x, v.y);
        __half2 hi = __floats2half2_rn(v.z, v.w);
        uint2 u;
        u.x = *(unsigned*)&lo;
        u.y = *(unsigned*)&hi;
        ((uint2*)out)[i] = u;
    }
}

// ---------------------------------------------------------------------------
// W prep: g_Wh[n][k] = Wcat[k][n] = (n<128) ? W1[k][n] : W1[k+128][n-128]
// ---------------------------------------------------------------------------
__global__ void w_prep_kernel(const float* __restrict__ W1, __half* __restrict__ Wh) {
    int idx = blockIdx.x * blockDim.x + threadIdx.x;   // over 256*128 = 32768
    if (idx < 256 * 128) {
        int r = idx >> 7;      // W1 row 0..255
        int c = idx & 127;     // W1 col 0..127
        float v = W1[idx];
        int k = r & 127;
        int n = c + ((r >> 7) << 7);
        Wh[n * 128 + k] = __float2half_rn(v);
    }
}

// ---------------------------------------------------------------------------
// Mean neighbor aggregation, fp16: one warp = 2 nodes, HADD2 accumulate.
// ---------------------------------------------------------------------------
__global__ void agg_kernel(const __half* __restrict__ in,
                           const int* __restrict__ nbr,
                           __half* __restrict__ out, int N) {
    int gw = (blockIdx.x * blockDim.x + threadIdx.x) >> 5;
    int lane = threadIdx.x & 31;
    int node = gw * 2 + (lane >> 4);
    if (node >= N) return;
    int sl = lane & 15;
    const int* nb = nbr + (size_t)node * KNBR;
    const uint4* in16 = (const uint4*)in;
    __half2 z = __float2half2_rn(0.f);
    __half2 a0 = z, a1 = z, a2 = z, a3 = z;
#pragma unroll
    for (int k = 0; k < KNBR; k++) {
        int idx = __ldg(nb + k);
        uint4 v = __ldg(in16 + (size_t)idx * 16 + sl);
        a0 = __hadd2(a0, *(__half2*)&v.x);
        a1 = __hadd2(a1, *(__half2*)&v.y);
        a2 = __hadd2(a2, *(__half2*)&v.z);
        a3 = __hadd2(a3, *(__half2*)&v.w);
    }
    __half2 s = __float2half2_rn(1.0f / (float)KNBR);
    a0 = __hmul2(a0, s); a1 = __hmul2(a1, s);
    a2 = __hmul2(a2, s); a3 = __hmul2(a3, s);
    uint4 r;
    r.x = *(unsigned*)&a0; r.y = *(unsigned*)&a1;
    r.z = *(unsigned*)&a2; r.w = *(unsigned*)&a3;
    ((uint4*)out)[(size_t)node * 16 + sl] = r;
}

// ---------------------------------------------------------------------------
// fp16 MMA + ldmatrix + cp.async helpers
// ---------------------------------------------------------------------------
__device__ __forceinline__ void mma_f16(float* d, const unsigned* a, const unsigned* b) {
    asm("mma.sync.aligned.m16n8k16.row.col.f32.f16.f16.f32 "
        "{%0,%1,%2,%3}, {%4,%5,%6,%7}, {%8,%9}, {%0,%1,%2,%3};"
        : "+f"(d[0]), "+f"(d[1]), "+f"(d[2]), "+f"(d[3])
        : "r"(a[0]), "r"(a[1]), "r"(a[2]), "r"(a[3]), "r"(b[0]), "r"(b[1]));
}

__device__ __forceinline__ void ldsm_x4(unsigned* r, unsigned addr) {
    asm volatile("ldmatrix.sync.aligned.m8n8.x4.shared.b16 {%0,%1,%2,%3}, [%4];"
                 : "=r"(r[0]), "=r"(r[1]), "=r"(r[2]), "=r"(r[3]) : "r"(addr));
}

__device__ __forceinline__ void cp_async16(unsigned dst, const void* src, int src_bytes) {
    asm volatile("cp.async.cg.shared.global [%0], [%1], 16, %2;"
                 :: "r"(dst), "l"(src), "r"(src_bytes) : "memory");
}

// ---------------------------------------------------------------------------
// C[N,256] = H[N,128] @ Wcat[128,256]   (fp16 in, fp32 acc, fp16 out)
// N-split: CTA handles a fixed 128-col half (bid&1). CTA tile: 64 x 128.
// Ws [128n][136h] = 34.8KB; Hs double-buffered 2 x [64m][136h] = 34.8KB
//   -> 69.6KB/CTA -> 3 CTAs/SM, 24 warps/SM.
// H tiles loaded via cp.async (zero-fill OOB), 2-stage pipeline, 1 barrier/tile.
// Warps 2(m) x 4(n); warp tile 32x32; acc = 2x4 frags (32 regs).
// ---------------------------------------------------------------------------
extern __shared__ unsigned s_dyn_u[];

__global__ __launch_bounds__(256, 3) void gemm_kernel(const __half* __restrict__ H,
                                                      const __half* __restrict__ Wh,
                                                      __half* __restrict__ C, int N) {
    unsigned* Ws  = s_dyn_u;                         // words; halves [128][136]
    unsigned* Hs0 = s_dyn_u + 128 * HSW;             // words; halves [64][136]
    unsigned* Hs1 = Hs0 + 64 * HSW;
    int t = threadIdx.x;
    int lane = t & 31;
    int warp = t >> 5;
    int mwarp = warp >> 2;      // 0..1
    int nwarp = warp & 3;       // 0..3
    int g  = lane >> 2;
    int tg = lane & 3;
    int n0 = nwarp * 32;
    int half = blockIdx.x & 1;

    // Fill Ws for this half from pre-converted fp16 Wh[n][k] (vectorized)
    {
        const uint4* W16 = (const uint4*)(Wh + (size_t)half * 128 * 128);
#pragma unroll
        for (int j = 0; j < 8; j++) {
            int i = t + j * 256;       // over 128 rows x 16 uint4
            int n = i >> 4;
            int q = i & 15;
            uint4 v = __ldg(W16 + i);
            *(uint4*)(Ws + n * HSW + q * 4) = v;
        }
    }

    unsigned hs0_b = (unsigned)__cvta_generic_to_shared(Hs0);
    unsigned hs1_b = (unsigned)__cvta_generic_to_shared(Hs1);
    unsigned ws_base = (unsigned)__cvta_generic_to_shared(Ws);
    unsigned a_row  = lane & 15;
    unsigned a_koff = (lane >> 4) * 8;
    unsigned b_n    = (lane & 7) + ((lane >> 4) << 3);
    unsigned b_koff = ((lane >> 3) & 1) << 3;

    int numRowTiles = (N + 63) >> 6;
    int stride = gridDim.x >> 1;
    int rt0 = blockIdx.x >> 1;

    // Per-thread load slot: i = t + j*256, row = i>>4, q = i&15
    const uint4* H16 = (const uint4*)H;

    // Prologue: issue cp.async for first tile into Hs0
    if (rt0 < numRowTiles) {
        int row0 = rt0 * 64;
#pragma unroll
        for (int j = 0; j < 4; j++) {
            int i = t + j * 256;
            int row = i >> 4, q = i & 15;
            unsigned dst = hs0_b + (unsigned)(row * HSW + q * 4) * 4;
            const uint4* src = H16 + (size_t)(row0 + row) * 16 + q;
            cp_async16(dst, src, (row0 + row < N) ? 16 : 0);
        }
    }
    asm volatile("cp.async.commit_group;" ::: "memory");

    int cur = 0;
    for (int rt = rt0; rt < numRowTiles; rt += stride) {
        int row0 = rt * 64;
        asm volatile("cp.async.wait_group 0;" ::: "memory");
        __syncthreads();   // current tile data visible to all; prev compute done

        // Issue cp.async for the NEXT tile into the other buffer
        int rtn = rt + stride;
        unsigned nxt_b = cur ? hs0_b : hs1_b;
        if (rtn < numRowTiles) {
            int rown0 = rtn * 64;
#pragma unroll
            for (int j = 0; j < 4; j++) {
                int i = t + j * 256;
                int row = i >> 4, q = i & 15;
                unsigned dst = nxt_b + (unsigned)(row * HSW + q * 4) * 4;
                const uint4* src = H16 + (size_t)(rown0 + row) * 16 + q;
                cp_async16(dst, src, (rown0 + row < N) ? 16 : 0);
            }
        }
        asm volatile("cp.async.commit_group;" ::: "memory");

        unsigned hs_base = cur ? hs1_b : hs0_b;

        float acc[2][4][4];
#pragma unroll
        for (int mf = 0; mf < 2; mf++)
#pragma unroll
            for (int nf = 0; nf < 4; nf++)
#pragma unroll
                for (int e = 0; e < 4; e++) acc[mf][nf][e] = 0.f;

#pragma unroll
        for (int kk = 0; kk < 8; kk++) {   // 8 chunks of K=16
            unsigned k0 = kk * 16;         // halves
            unsigned a[2][4];
#pragma unroll
            for (int mf = 0; mf < 2; mf++) {
                unsigned addr = hs_base +
                    ((mwarp * 32 + mf * 16 + a_row) * (2 * HSW) + k0 + a_koff) * 2;
                ldsm_x4(a[mf], addr);
            }
            unsigned b[4][2];
            {
                unsigned addr1 = ws_base +
                    ((n0 + b_n) * (2 * HSW) + k0 + b_koff) * 2;
                unsigned r1[4], r2[4];
                ldsm_x4(r1, addr1);                       // nf 0,1
                ldsm_x4(r2, addr1 + 16 * (2 * HSW) * 2);  // nf 2,3
                b[0][0] = r1[0]; b[0][1] = r1[1];
                b[1][0] = r1[2]; b[1][1] = r1[3];
                b[2][0] = r2[0]; b[2][1] = r2[1];
                b[3][0] = r2[2]; b[3][1] = r2[3];
            }
#pragma unroll
            for (int mf = 0; mf < 2; mf++)
#pragma unroll
                for (int nf = 0; nf < 4; nf++)
                    mma_f16(acc[mf][nf], a[mf], b[nf]);
        }

        // Epilogue -> fp16 C. c0,c1 at (g, 2tg), c2,c3 at (g+8, 2tg)
        unsigned* C32 = (unsigned*)C;   // half2 units; row = 128 half2
#pragma unroll
        for (int mf = 0; mf < 2; mf++) {
            int r_lo = row0 + mwarp * 32 + mf * 16 + g;
            int r_hi = r_lo + 8;
#pragma unroll
            for (int nf = 0; nf < 4; nf++) {
                int colh = (half * 128 + n0 + nf * 8 + tg * 2) >> 1;
                if (r_lo < N) {
                    __half2 h = __floats2half2_rn(acc[mf][nf][0], acc[mf][nf][1]);
                    C32[(size_t)r_lo * 128 + colh] = *(unsigned*)&h;
                }
                if (r_hi < N) {
                    __half2 h = __floats2half2_rn(acc[mf][nf][2], acc[mf][nf][3]);
                    C32[(size_t)r_hi * 128 + colh] = *(unsigned*)&h;
                }
            }
        }
        cur ^= 1;
    }
}

// ---------------------------------------------------------------------------
// Per-pair loss: one warp per pair (grid-strided), C is fp16
// ---------------------------------------------------------------------------
__global__ void pair_kernel(const int* __restrict__ pairs,
                            const int* __restrict__ labels,
                            const __half* __restrict__ C,
                            const float* __restrict__ b1,
                            const float* __restrict__ W2,
                            const float* __restrict__ b2,
                            float* __restrict__ out, int B) {
    int lane = threadIdx.x & 31;
    int wib = threadIdx.x >> 5;
    int warpsPerBlock = blockDim.x >> 5;
    int gwarp = blockIdx.x * warpsPerBlock + wib;
    int nwarps = gridDim.x * warpsPerBlock;

    float4 bias = __ldg((const float4*)b1 + lane);
    float w20[4], w21[4];
#pragma unroll
    for (int q = 0; q < 4; q++) {
        w20[q] = __ldg(W2 + (lane * 4 + q) * 2 + 0);
        w21[q] = __ldg(W2 + (lane * 4 + q) * 2 + 1);
    }
    float b2_0 = __ldg(b2 + 0), b2_1 = __ldg(b2 + 1);

    const uint2* C8 = (const uint2*)C;
    float lsum = 0.f;

    for (int p = gwarp; p < B; p += nwarps) {
        int src = __ldg(pairs + 2 * p);
        int dst = __ldg(pairs + 2 * p + 1);
        uint2 ua = __ldg(C8 + (size_t)src * 64 + lane);
        uint2 ub = __ldg(C8 + (size_t)dst * 64 + 32 + lane);
        float2 a01 = __half22float2(*(__half2*)&ua.x);
        float2 a23 = __half22float2(*(__half2*)&ua.y);
        float2 c01 = __half22float2(*(__half2*)&ub.x);
        float2 c23 = __half22float2(*(__half2*)&ub.y);
        float h0 = fmaxf(a01.x + c01.x + bias.x, 0.f);
        float h1 = fmaxf(a01.y + c01.y + bias.y, 0.f);
        float h2 = fmaxf(a23.x + c23.x + bias.z, 0.f);
        float h3 = fmaxf(a23.y + c23.y + bias.w, 0.f);
        float l0 = h0 * w20[0] + h1 * w20[1] + h2 * w20[2] + h3 * w20[3];
        float l1 = h0 * w21[0] + h1 * w21[1] + h2 * w21[2] + h3 * w21[3];
#pragma unroll
        for (int off = 16; off > 0; off >>= 1) {
            l0 += __shfl_down_sync(0xFFFFFFFFu, l0, off);
            l1 += __shfl_down_sync(0xFFFFFFFFu, l1, off);
        }
        if (lane == 0) {
            l0 += b2_0; l1 += b2_1;
            float m = fmaxf(l0, l1);
            float e0 = expf(l0 - m), e1 = expf(l1 - m);
            float inv = 1.f / (e0 + e1);
            float p0 = e0 * inv, p1 = e1 * inv;
            float mm = fmaxf(p0, p1);
            float lse = mm + logf(expf(p0 - mm) + expf(p1 - mm));
            int lab = __ldg(labels + p);
            float pl = lab ? p1 : p0;
            lsum += (lse - pl);
        }
    }

    __shared__ float ssum[32];
    if (lane == 0) ssum[wib] = lsum;
    __syncthreads();
    if (threadIdx.x == 0) {
        float s = 0.f;
        for (int w = 0; w < warpsPerBlock; w++) s += ssum[w];
        atomicAdd(out, s / (float)B);
    }
}

// ---------------------------------------------------------------------------
extern "C" void kernel_launch(void* const* d_in, const int* in_sizes, int n_in,
                              void* d_out, int out_size) {
    const int*   pairs     = (const int*)d_in[0];
    const int*   labels    = (const int*)d_in[1];
    const int*   neighbors = (const int*)d_in[2];
    const float* embedding = (const float*)d_in[3];
    const float* W1        = (const float*)d_in[4];
    const float* b1        = (const float*)d_in[5];
    const float* W2        = (const float*)d_in[6];
    const float* b2        = (const float*)d_in[7];

    int B = in_sizes[0] / 2;
    int N = in_sizes[2] / KNBR;

    __half *E, *H1, *H2, *C, *Wh;
    cudaGetSymbolAddress((void**)&E,  g_E);
    cudaGetSymbolAddress((void**)&H1, g_H1);
    cudaGetSymbolAddress((void**)&H2, g_H2);
    cudaGetSymbolAddress((void**)&C,  g_C);
    cudaGetSymbolAddress((void**)&Wh, g_Wh);

    float* out = (float*)d_out;

    // Convert embedding to fp16 (also zeroes the loss accumulator)
    int n4 = N * DIM / 4;
    f2h_kernel<<<(n4 + 255) / 256, 256>>>(embedding, E, n4, out, out_size);

    // Prepare Wcat^T fp16
    w_prep_kernel<<<128, 256>>>(W1, Wh);

    // 2 aggregation layers
    int aggBlocks = (N / 2 + 7) / 8;
    agg_kernel<<<aggBlocks, 256>>>(E,  neighbors, H1, N);
    agg_kernel<<<aggBlocks, 256>>>(H1, neighbors, H2, N);

    // Projection GEMM: N-split halves, 3 CTAs/SM, cp.async double-buffer
    size_t smem = (size_t)(128 * HSW + 2 * 64 * HSW) * sizeof(unsigned);  // 69632 B
    cudaFuncSetAttribute(gemm_kernel, cudaFuncAttributeMaxDynamicSharedMemorySize, (int)smem);
    gemm_kernel<<<444, 256, smem>>>(H2, Wh, C, N);

    // Pair loss (fp16 C gathers)
    pair_kernel<<<1184, 256>>>(pairs, labels, C, b1, W2, b2, out, B);
}

// round 9
// speedup vs baseline: 1.3040x; 1.0263x over previous
#include <cuda_runtime.h>
#include <cuda_fp16.h>
#include <cuda_bf16.h>
#include <math.h>

#define NMAX 50000
#define DIM 128
#define KNBR 16
#define HSW 68   // smem row stride in 32-bit words (64 data + 4 pad; 68%32==4)

// Scratch (static device globals — no allocation allowed)
__device__ __half g_E [(size_t)NMAX * DIM];
__device__ __half g_H1[(size_t)NMAX * DIM];
__device__ __half g_C [(size_t)NMAX * 2 * DIM];
__device__ __half g_Wh[256 * 128];   // Wcat^T as [n][k] fp16, row-major

// ---------------------------------------------------------------------------
// fp32 -> fp16 elementwise convert (vectorized); also zeroes the output scalar
// ---------------------------------------------------------------------------
__global__ void f2h_kernel(const float* __restrict__ in, __half* __restrict__ out,
                           int n4, float* __restrict__ loss_out, int loss_n) {
    int i = blockIdx.x * blockDim.x + threadIdx.x;
    if (blockIdx.x == 0 && threadIdx.x < (unsigned)loss_n) loss_out[threadIdx.x] = 0.f;
    if (i < n4) {
        float4 v = __ldg((const float4*)in + i);
        __half2 lo = __floats2half2_rn(v.x, v.y);
        __half2 hi = __floats2half2_rn(v.z, v.w);
        uint2 u;
        u.x = *(unsigned*)&lo;
        u.y = *(unsigned*)&hi;
        ((uint2*)out)[i] = u;
    }
}

// ---------------------------------------------------------------------------
// W prep: g_Wh[n][k] = Wcat[k][n] = (n<128) ? W1[k][n] : W1[k+128][n-128]
// ---------------------------------------------------------------------------
__global__ void w_prep_kernel(const float* __restrict__ W1, __half* __restrict__ Wh) {
    int idx = blockIdx.x * blockDim.x + threadIdx.x;   // over 256*128 = 32768
    if (idx < 256 * 128) {
        int r = idx >> 7;      // W1 row 0..255
        int c = idx & 127;     // W1 col 0..127
        float v = W1[idx];
        int k = r & 127;
        int n = c + ((r >> 7) << 7);
        Wh[n * 128 + k] = __float2half_rn(v);
    }
}

// ---------------------------------------------------------------------------
// Mean neighbor aggregation (layer 1), fp16: warp = 2 nodes, HADD2 accumulate.
// ---------------------------------------------------------------------------
__global__ void agg_kernel(const __half* __restrict__ in,
                           const int* __restrict__ nbr,
                           __half* __restrict__ out, int N) {
    int gw = (blockIdx.x * blockDim.x + threadIdx.x) >> 5;
    int lane = threadIdx.x & 31;
    int node = gw * 2 + (lane >> 4);
    if (node >= N) return;
    int sl = lane & 15;
    const int* nb = nbr + (size_t)node * KNBR;
    const uint4* in16 = (const uint4*)in;
    __half2 z = __float2half2_rn(0.f);
    __half2 a0 = z, a1 = z, a2 = z, a3 = z;
#pragma unroll
    for (int k = 0; k < KNBR; k++) {
        int idx = __ldg(nb + k);
        uint4 v = __ldg(in16 + (size_t)idx * 16 + sl);
        a0 = __hadd2(a0, *(__half2*)&v.x);
        a1 = __hadd2(a1, *(__half2*)&v.y);
        a2 = __hadd2(a2, *(__half2*)&v.z);
        a3 = __hadd2(a3, *(__half2*)&v.w);
    }
    __half2 s = __float2half2_rn(1.0f / (float)KNBR);
    a0 = __hmul2(a0, s); a1 = __hmul2(a1, s);
    a2 = __hmul2(a2, s); a3 = __hmul2(a3, s);
    uint4 r;
    r.x = *(unsigned*)&a0; r.y = *(unsigned*)&a1;
    r.z = *(unsigned*)&a2; r.w = *(unsigned*)&a3;
    ((uint4*)out)[(size_t)node * 16 + sl] = r;
}

// ---------------------------------------------------------------------------
// fp16 MMA + ldmatrix helpers
// ---------------------------------------------------------------------------
__device__ __forceinline__ void mma_f16(float* d, const unsigned* a, const unsigned* b) {
    asm("mma.sync.aligned.m16n8k16.row.col.f32.f16.f16.f32 "
        "{%0,%1,%2,%3}, {%4,%5,%6,%7}, {%8,%9}, {%0,%1,%2,%3};"
        : "+f"(d[0]), "+f"(d[1]), "+f"(d[2]), "+f"(d[3])
        : "r"(a[0]), "r"(a[1]), "r"(a[2]), "r"(a[3]), "r"(b[0]), "r"(b[1]));
}

__device__ __forceinline__ void ldsm_x4(unsigned* r, unsigned addr) {
    asm volatile("ldmatrix.sync.aligned.m8n8.x4.shared.b16 {%0,%1,%2,%3}, [%4];"
                 : "=r"(r[0]), "=r"(r[1]), "=r"(r[2]), "=r"(r[3]) : "r"(addr));
}

// ---------------------------------------------------------------------------
// FUSED agg-layer-2 + projection GEMM.
// Per 64-row tile: gather H2 rows from H1 (mean of 16 nbrs) into smem,
// then C[tile,256] = H2_tile @ Wcat via mma.sync.
// Ws full [256n][136 halves] = 69.6KB; Hs double-buffered 2x[64][136] = 34.8KB
//   -> 104.4KB/CTA -> 2 CTAs/SM.
// Warps 2(m) x 4(n); warp tile 32 x 64; acc = 2x8 frags (64 regs).
// Per loop iter: [barrier] [MMA on Hs[cur]] [agg next tile -> Hs[nxt]] [store C].
// ---------------------------------------------------------------------------
extern __shared__ unsigned s_dyn_u[];

__global__ __launch_bounds__(256, 2) void agg_gemm_kernel(const __half* __restrict__ H1,
                                                          const int* __restrict__ nbr,
                                                          const __half* __restrict__ Wh,
                                                          __half* __restrict__ C, int N) {
    unsigned* Ws  = s_dyn_u;                 // words; halves [256][136]
    unsigned* Hs0 = s_dyn_u + 256 * HSW;     // words; halves [64][136]
    unsigned* Hs1 = Hs0 + 64 * HSW;
    int t = threadIdx.x;
    int lane = t & 31;
    int warp = t >> 5;
    int mwarp = warp >> 2;      // 0..1
    int nwarp = warp & 3;       // 0..3
    int g  = lane >> 2;
    int tg = lane & 3;
    int n0 = nwarp * 64;

    // Fill Ws (all 256 cols) from pre-converted fp16 Wh[n][k] (vectorized)
    {
        const uint4* W16 = (const uint4*)Wh;
#pragma unroll
        for (int j = 0; j < 16; j++) {
            int i = t + j * 256;       // over 256 rows x 16 uint4
            int n = i >> 4;
            int q = i & 15;
            uint4 v = __ldg(W16 + i);
            *(uint4*)(Ws + n * HSW + q * 4) = v;
        }
    }

    unsigned hs0_b = (unsigned)__cvta_generic_to_shared(Hs0);
    unsigned hs1_b = (unsigned)__cvta_generic_to_shared(Hs1);
    unsigned ws_base = (unsigned)__cvta_generic_to_shared(Ws);
    unsigned a_row  = lane & 15;
    unsigned a_koff = (lane >> 4) * 8;
    unsigned b_n    = (lane & 7) + ((lane >> 4) << 3);
    unsigned b_koff = ((lane >> 3) & 1) << 3;

    int numRowTiles = (N + 63) >> 6;
    int stride = gridDim.x;
    int rt0 = blockIdx.x;

    // Agg helper variables
    int agg_sub  = lane >> 4;   // warp handles 2 rows per round
    int agg_sl   = lane & 15;
    const uint4* H1_16 = (const uint4*)H1;
    const __half2 hscale = __float2half2_rn(1.0f / (float)KNBR);

    // Prologue: aggregate first tile into Hs0
    if (rt0 < numRowTiles) {
        int row0 = rt0 * 64;
#pragma unroll
        for (int round = 0; round < 4; round++) {
            int r_local = round * 16 + warp * 2 + agg_sub;
            int node = row0 + r_local;
            __half2 z = __float2half2_rn(0.f);
            __half2 a0 = z, a1 = z, a2 = z, a3 = z;
            if (node < N) {
                const int* nb = nbr + (size_t)node * KNBR;
#pragma unroll
                for (int k = 0; k < KNBR; k++) {
                    int idx = __ldg(nb + k);
                    uint4 v = __ldg(H1_16 + (size_t)idx * 16 + agg_sl);
                    a0 = __hadd2(a0, *(__half2*)&v.x);
                    a1 = __hadd2(a1, *(__half2*)&v.y);
                    a2 = __hadd2(a2, *(__half2*)&v.z);
                    a3 = __hadd2(a3, *(__half2*)&v.w);
                }
                a0 = __hmul2(a0, hscale); a1 = __hmul2(a1, hscale);
                a2 = __hmul2(a2, hscale); a3 = __hmul2(a3, hscale);
            }
            uint4 r;
            r.x = *(unsigned*)&a0; r.y = *(unsigned*)&a1;
            r.z = *(unsigned*)&a2; r.w = *(unsigned*)&a3;
            *(uint4*)(Hs0 + r_local * HSW + agg_sl * 4) = r;
        }
    }

    int cur = 0;
    for (int rt = rt0; rt < numRowTiles; rt += stride) {
        int row0 = rt * 64;
        __syncthreads();   // Hs[cur] complete (prologue or previous iter's agg)

        unsigned hs_base = cur ? hs1_b : hs0_b;

        // --- MMA on Hs[cur] ---
        float acc[2][8][4];
#pragma unroll
        for (int mf = 0; mf < 2; mf++)
#pragma unroll
            for (int nf = 0; nf < 8; nf++)
#pragma unroll
                for (int e = 0; e < 4; e++) acc[mf][nf][e] = 0.f;

#pragma unroll
        for (int kk = 0; kk < 8; kk++) {   // 8 chunks of K=16
            unsigned k0 = kk * 16;         // halves
            unsigned a[2][4];
#pragma unroll
            for (int mf = 0; mf < 2; mf++) {
                unsigned addr = hs_base +
                    ((mwarp * 32 + mf * 16 + a_row) * (2 * HSW) + k0 + a_koff) * 2;
                ldsm_x4(a[mf], addr);
            }
            unsigned b[8][2];
#pragma unroll
            for (int j = 0; j < 4; j++) {
                unsigned addr = ws_base +
                    ((n0 + j * 16 + b_n) * (2 * HSW) + k0 + b_koff) * 2;
                unsigned r[4];
                ldsm_x4(r, addr);
                b[2 * j][0] = r[0]; b[2 * j][1] = r[1];
                b[2 * j + 1][0] = r[2]; b[2 * j + 1][1] = r[3];
            }
#pragma unroll
            for (int mf = 0; mf < 2; mf++)
#pragma unroll
                for (int nf = 0; nf < 8; nf++)
                    mma_f16(acc[mf][nf], a[mf], b[nf]);
        }

        // --- Aggregate NEXT tile into Hs[nxt] (overlaps other warps' MMA) ---
        int rtn = rt + stride;
        if (rtn < numRowTiles) {
            unsigned* Hn = cur ? Hs0 : Hs1;
            int rown0 = rtn * 64;
#pragma unroll
            for (int round = 0; round < 4; round++) {
                int r_local = round * 16 + warp * 2 + agg_sub;
                int node = rown0 + r_local;
                __half2 z = __float2half2_rn(0.f);
                __half2 a0 = z, a1 = z, a2 = z, a3 = z;
                if (node < N) {
                    const int* nb = nbr + (size_t)node * KNBR;
#pragma unroll
                    for (int k = 0; k < KNBR; k++) {
                        int idx = __ldg(nb + k);
                        uint4 v = __ldg(H1_16 + (size_t)idx * 16 + agg_sl);
                        a0 = __hadd2(a0, *(__half2*)&v.x);
                        a1 = __hadd2(a1, *(__half2*)&v.y);
                        a2 = __hadd2(a2, *(__half2*)&v.z);
                        a3 = __hadd2(a3, *(__half2*)&v.w);
                    }
                    a0 = __hmul2(a0, hscale); a1 = __hmul2(a1, hscale);
                    a2 = __hmul2(a2, hscale); a3 = __hmul2(a3, hscale);
                }
                uint4 r;
                r.x = *(unsigned*)&a0; r.y = *(unsigned*)&a1;
                r.z = *(unsigned*)&a2; r.w = *(unsigned*)&a3;
                *(uint4*)(Hn + r_local * HSW + agg_sl * 4) = r;
            }
        }

        // --- Epilogue -> fp16 C. c0,c1 at (g, 2tg), c2,c3 at (g+8, 2tg) ---
        unsigned* C32 = (unsigned*)C;   // half2 units; row = 128 half2
#pragma unroll
        for (int mf = 0; mf < 2; mf++) {
            int r_lo = row0 + mwarp * 32 + mf * 16 + g;
            int r_hi = r_lo + 8;
#pragma unroll
            for (int nf = 0; nf < 8; nf++) {
                int colh = (n0 + nf * 8 + tg * 2) >> 1;
                if (r_lo < N) {
                    __half2 h = __floats2half2_rn(acc[mf][nf][0], acc[mf][nf][1]);
                    C32[(size_t)r_lo * 128 + colh] = *(unsigned*)&h;
                }
                if (r_hi < N) {
                    __half2 h = __floats2half2_rn(acc[mf][nf][2], acc[mf][nf][3]);
                    C32[(size_t)r_hi * 128 + colh] = *(unsigned*)&h;
                }
            }
        }
        cur ^= 1;
    }
}

// ---------------------------------------------------------------------------
// Per-pair loss: one warp handles TWO pairs (lanes 0-15 / 16-31).
// Each lane owns 8 features (uint4 loads). C is fp16 [N][256].
// ---------------------------------------------------------------------------
__global__ void pair_kernel(const int* __restrict__ pairs,
                            const int* __restrict__ labels,
                            const __half* __restrict__ C,
                            const float* __restrict__ b1,
                            const float* __restrict__ W2,
                            const float* __restrict__ b2,
                            float* __restrict__ out, int B) {
    int lane = threadIdx.x & 31;
    int sl = lane & 15;
    int side = lane >> 4;
    int wib = threadIdx.x >> 5;
    int warpsPerBlock = blockDim.x >> 5;
    int gwarp = blockIdx.x * warpsPerBlock + wib;
    int nwarps = gridDim.x * warpsPerBlock;

    // Per-lane constants: features 8*sl .. 8*sl+7
    float4 b_lo = __ldg((const float4*)b1 + 2 * sl);
    float4 b_hi = __ldg((const float4*)b1 + 2 * sl + 1);
    float bias[8] = {b_lo.x, b_lo.y, b_lo.z, b_lo.w, b_hi.x, b_hi.y, b_hi.z, b_hi.w};
    float w20[8], w21[8];
#pragma unroll
    for (int q = 0; q < 8; q++) {
        w20[q] = __ldg(W2 + (sl * 8 + q) * 2 + 0);
        w21[q] = __ldg(W2 + (sl * 8 + q) * 2 + 1);
    }
    float b2_0 = __ldg(b2 + 0), b2_1 = __ldg(b2 + 1);

    const uint4* C16 = (const uint4*)C;   // 32 uint4 per 256-half row
    float lsum = 0.f;

    for (int p = gwarp * 2 + side; p < B; p += nwarps * 2) {
        int src = __ldg(pairs + 2 * p);
        int dst = __ldg(pairs + 2 * p + 1);
        uint4 ua = __ldg(C16 + (size_t)src * 32 + sl);        // cols 8sl..8sl+7
        uint4 ub = __ldg(C16 + (size_t)dst * 32 + 16 + sl);   // cols 128+8sl..
        float l0 = 0.f, l1 = 0.f;
        const unsigned* au = (const unsigned*)&ua;
        const unsigned* bu = (const unsigned*)&ub;
#pragma unroll
        for (int c = 0; c < 4; c++) {
            float2 af = __half22float2(*(__half2*)&au[c]);
            float2 bf = __half22float2(*(__half2*)&bu[c]);
            float h0 = fmaxf(af.x + bf.x + bias[2 * c], 0.f);
            float h1 = fmaxf(af.y + bf.y + bias[2 * c + 1], 0.f);
            l0 += h0 * w20[2 * c] + h1 * w20[2 * c + 1];
            l1 += h0 * w21[2 * c] + h1 * w21[2 * c + 1];
        }
#pragma unroll
        for (int off = 8; off > 0; off >>= 1) {
            l0 += __shfl_xor_sync(0xFFFFFFFFu, l0, off);
            l1 += __shfl_xor_sync(0xFFFFFFFFu, l1, off);
        }
        if (sl == 0) {
            l0 += b2_0; l1 += b2_1;
            float m = fmaxf(l0, l1);
            float e0 = expf(l0 - m), e1 = expf(l1 - m);
            float inv = 1.f / (e0 + e1);
            float p0 = e0 * inv, p1 = e1 * inv;
            float mm = fmaxf(p0, p1);
            float lse = mm + logf(expf(p0 - mm) + expf(p1 - mm));
            int lab = __ldg(labels + p);
            float pl = lab ? p1 : p0;
            lsum += (lse - pl);
        }
    }

    // lsum lives on lanes 0 and 16 — combine, then block-reduce
    lsum += __shfl_down_sync(0xFFFFFFFFu, lsum, 16);
    __shared__ float ssum[32];
    if (lane == 0) ssum[wib] = lsum;
    __syncthreads();
    if (threadIdx.x == 0) {
        float s = 0.f;
        for (int w = 0; w < warpsPerBlock; w++) s += ssum[w];
        atomicAdd(out, s / (float)B);
    }
}

// ---------------------------------------------------------------------------
extern "C" void kernel_launch(void* const* d_in, const int* in_sizes, int n_in,
                              void* d_out, int out_size) {
    const int*   pairs     = (const int*)d_in[0];
    const int*   labels    = (const int*)d_in[1];
    const int*   neighbors = (const int*)d_in[2];
    const float* embedding = (const float*)d_in[3];
    const float* W1        = (const float*)d_in[4];
    const float* b1        = (const float*)d_in[5];
    const float* W2        = (const float*)d_in[6];
    const float* b2        = (const float*)d_in[7];

    int B = in_sizes[0] / 2;
    int N = in_sizes[2] / KNBR;

    __half *E, *H1, *C, *Wh;
    cudaGetSymbolAddress((void**)&E,  g_E);
    cudaGetSymbolAddress((void**)&H1, g_H1);
    cudaGetSymbolAddress((void**)&C,  g_C);
    cudaGetSymbolAddress((void**)&Wh, g_Wh);

    float* out = (float*)d_out;

    // Convert embedding to fp16 (also zeroes the loss accumulator)
    int n4 = N * DIM / 4;
    f2h_kernel<<<(n4 + 255) / 256, 256>>>(embedding, E, n4, out, out_size);

    // Prepare Wcat^T fp16
    w_prep_kernel<<<128, 256>>>(W1, Wh);

    // Aggregation layer 1
    int aggBlocks = (N / 2 + 7) / 8;
    agg_kernel<<<aggBlocks, 256>>>(E, neighbors, H1, N);

    // Fused agg layer 2 + projection GEMM (2 CTAs/SM)
    size_t smem = (size_t)(256 * HSW + 2 * 64 * HSW) * sizeof(unsigned);  // 104448 B
    cudaFuncSetAttribute(agg_gemm_kernel, cudaFuncAttributeMaxDynamicSharedMemorySize, (int)smem);
    agg_gemm_kernel<<<296, 256, smem>>>(H1, neighbors, Wh, C, N);

    // Pair loss (2 pairs per warp, fp16 C gathers)
    pair_kernel<<<1184, 256>>>(pairs, labels, C, b1, W2, b2, out, B);
}